// round 12
// baseline (speedup 1.0000x reference)
#include <cuda_runtime.h>
#include <math.h>

#define BB 2
#define SS 2048
#define DD 1024
#define HH 16
#define DH 64
#define MM (BB * SS)   // 4096

// Scratch. ALL inter-kernel tensors hold TF32 BIT PATTERNS (same size as
// fp32, converted once): g_xt = x, g_wt[4] = wq/wk/wv/wo, g_q (pre-scaled
// 1/8) / g_k / g_v from the QKV epilogue, g_att from the attention epilogue.
__device__ unsigned g_xt[MM * DD];
__device__ unsigned g_wt[4][DD * DD];
__device__ unsigned g_q[BB * HH * SS * DH];
__device__ unsigned g_k[BB * HH * SS * DH];
__device__ unsigned g_v[BB * HH * SS * DH];
__device__ unsigned g_att[MM * DD];

// ---------------------------------------------------------------------------
// tf32 helpers
// ---------------------------------------------------------------------------
__device__ __forceinline__ unsigned f2tf32(float x) {
    unsigned r;
    asm("cvt.rna.tf32.f32 %0, %1;\n" : "=r"(r) : "f"(x));
    return r;
}
__device__ __forceinline__ void mma_tf32(float& c0, float& c1, float& c2, float& c3,
                                         unsigned a0, unsigned a1, unsigned a2, unsigned a3,
                                         unsigned b0, unsigned b1) {
    asm volatile(
        "mma.sync.aligned.m16n8k8.row.col.f32.tf32.tf32.f32 "
        "{%0,%1,%2,%3}, {%4,%5,%6,%7}, {%8,%9}, {%0,%1,%2,%3};\n"
        : "+f"(c0), "+f"(c1), "+f"(c2), "+f"(c3)
        : "r"(a0), "r"(a1), "r"(a2), "r"(a3), "r"(b0), "r"(b1));
}

// cp.async helpers
__device__ __forceinline__ unsigned smem_u32(const void* p) {
    return (unsigned)__cvta_generic_to_shared(p);
}
__device__ __forceinline__ void cp16(unsigned s, const void* g) {
    asm volatile("cp.async.cg.shared.global [%0], [%1], 16;\n" :: "r"(s), "l"(g));
}
#define CP_COMMIT() asm volatile("cp.async.commit_group;\n" ::: "memory")
#define CP_WAIT1()  asm volatile("cp.async.wait_group 1;\n" ::: "memory")

// ---------------------------------------------------------------------------
// Pre-convert x and the 4 weight matrices to tf32 bits (same footprint).
// 2M float4 work items: first 1M = x, next 1M = wq|wk|wv|wo.
// ---------------------------------------------------------------------------
__global__ void __launch_bounds__(256) preconv(const float* __restrict__ x,
                                               const float* __restrict__ wq,
                                               const float* __restrict__ wk,
                                               const float* __restrict__ wv,
                                               const float* __restrict__ wo) {
    unsigned idx = blockIdx.x * 256 + threadIdx.x;   // 0 .. 2M-1
    const float* src;
    unsigned* dst;
    unsigned off;
    if (idx < (1u << 20)) {
        src = x; dst = g_xt; off = idx;
    } else {
        unsigned i2 = idx - (1u << 20);
        unsigned w = i2 >> 18;          // 262144 float4 per W
        off = i2 & 0x3FFFFu;
        src = (w == 0) ? wq : (w == 1) ? wk : (w == 2) ? wv : wo;
        dst = g_wt[w];
    }
    float4 v = *(const float4*)(src + off * 4);
    *(uint4*)(dst + off * 4) =
        make_uint4(f2tf32(v.x), f2tf32(v.y), f2tf32(v.z), f2tf32(v.w));
}

// ---------------------------------------------------------------------------
// NT GEMM, single-tf32 x single-tf32, operands pre-converted to tf32 bits:
// the hot loop is pure LDS + HMMA. cp.async double-buffered tiles.
// C[m,n] = sum_k A[m,k] * W[n,k] (+bias).
// Block tile 128x128, 8 warps, warp tile 32(m)x64(n), k-chunk 32.
// mode 0: fused QKV. A = g_xt, blockIdx.z picks g_wt[0..2]; outputs as tf32
//         bits into g_q (scaled 1/8) / g_k / g_v, [B,H,S,Dh] layout.
// mode 3: A = g_att (tf32 bits), W = g_wt[3], out -> Cext fp32 + bias.
// ---------------------------------------------------------------------------
__global__ void __launch_bounds__(256, 2) gemm_tf32(const float* __restrict__ bias,
                                                    float* __restrict__ Cext,
                                                    int mode) {
    __shared__ unsigned As[2][128][36];
    __shared__ unsigned Ws[2][128][36];

    const int t    = threadIdx.x;
    const int lane = t & 31;
    const int warp = t >> 5;
    const int wm   = warp >> 1;      // 0..3  (m position)
    const int wn   = warp & 1;       // 0..1  (n position)
    const int g    = lane >> 2;      // groupID 0..7
    const int tg   = lane & 3;       // thread in group 0..3

    const int m0 = blockIdx.y * 128;
    const int n0 = blockIdx.x * 128;
    const int z  = blockIdx.z;

    const unsigned* Ap = (mode == 3) ? g_att : g_xt;
    const unsigned* Wp = (mode == 3) ? g_wt[3] : g_wt[z];
    unsigned* Cq = (z == 0) ? g_q : (z == 1) ? g_k : g_v;

    auto load_chunk = [&](int k0, int bufi) {
#pragma unroll
        for (int i = 0; i < 4; i++) {
            int idx = t + i * 256;
            int row = idx >> 3;
            int fc  = (idx & 7) * 4;
            cp16(smem_u32(&As[bufi][row][fc]), Ap + (size_t)(m0 + row) * 1024 + k0 + fc);
            cp16(smem_u32(&Ws[bufi][row][fc]), Wp + (size_t)(n0 + row) * 1024 + k0 + fc);
        }
    };

    float c[2][8][4];
#pragma unroll
    for (int mi = 0; mi < 2; mi++)
#pragma unroll
        for (int ni = 0; ni < 8; ni++)
#pragma unroll
            for (int e = 0; e < 4; e++) c[mi][ni][e] = 0.f;

    load_chunk(0, 0);  CP_COMMIT();
    load_chunk(32, 1); CP_COMMIT();

    for (int kc = 0; kc < 32; kc++) {
        CP_WAIT1();
        __syncthreads();
        const int bi = kc & 1;

#pragma unroll
        for (int kk = 0; kk < 4; kk++) {
            const int kb = kk * 8;
            unsigned ah[2][4], bh[8][2];
#pragma unroll
            for (int mi = 0; mi < 2; mi++) {
                const int rb = wm * 32 + mi * 16;
                ah[mi][0] = As[bi][rb + g][kb + tg];
                ah[mi][1] = As[bi][rb + g + 8][kb + tg];
                ah[mi][2] = As[bi][rb + g][kb + tg + 4];
                ah[mi][3] = As[bi][rb + g + 8][kb + tg + 4];
            }
#pragma unroll
            for (int ni = 0; ni < 8; ni++) {
                const int nb = wn * 64 + ni * 8;
                bh[ni][0] = Ws[bi][nb + g][kb + tg];
                bh[ni][1] = Ws[bi][nb + g][kb + tg + 4];
            }
#pragma unroll
            for (int mi = 0; mi < 2; mi++)
#pragma unroll
                for (int ni = 0; ni < 8; ni++) {
                    mma_tf32(c[mi][ni][0], c[mi][ni][1], c[mi][ni][2], c[mi][ni][3],
                             ah[mi][0], ah[mi][1], ah[mi][2], ah[mi][3],
                             bh[ni][0], bh[ni][1]);
                }
        }

        __syncthreads();
        if (kc < 30) load_chunk((kc + 2) * 32, bi);
        CP_COMMIT();
    }

    // Epilogue. mode 0: write tf32 bits (Q pre-scaled 1/8). mode 3: fp32+bias.
#pragma unroll
    for (int mi = 0; mi < 2; mi++) {
#pragma unroll
        for (int ni = 0; ni < 8; ni++) {
            int mA = m0 + wm * 32 + mi * 16 + g;
            int mB = mA + 8;
            int n  = n0 + wn * 64 + ni * 8 + 2 * tg;
            if (mode == 3) {
                float bx = bias[n], by = bias[n + 1];
                *(float2*)(Cext + (size_t)mA * 1024 + n) =
                    make_float2(c[mi][ni][0] + bx, c[mi][ni][1] + by);
                *(float2*)(Cext + (size_t)mB * 1024 + n) =
                    make_float2(c[mi][ni][2] + bx, c[mi][ni][3] + by);
            } else {
                int h  = n >> 6;
                int dh = n & 63;
                float sc = (z == 0) ? 0.125f : 1.0f;
                {
                    int b = mA >> 11, s = mA & 2047;
                    *(uint2*)(Cq + (size_t)((b * HH + h) * SS + s) * DH + dh) =
                        make_uint2(f2tf32(c[mi][ni][0] * sc), f2tf32(c[mi][ni][1] * sc));
                }
                {
                    int b = mB >> 11, s = mB & 2047;
                    *(uint2*)(Cq + (size_t)((b * HH + h) * SS + s) * DH + dh) =
                        make_uint2(f2tf32(c[mi][ni][2] * sc), f2tf32(c[mi][ni][3] * sc));
                }
            }
        }
    }
}

// ---------------------------------------------------------------------------
// Flash attention via tensor cores, cp.async double-buffered K/V tiles.
// Block = 64 query rows, 4 warps (16 rows each), 64-key tiles through SMEM.
// Q/K/V arrive as tf32 bits -> hot loop is pure LDS + HMMA.
// QK^T: single tf32. P*V: tf32 via SMEM Ps round-trip.
// Writes g_att as tf32 bits (consumed bit-exactly by the O-projection).
// ---------------------------------------------------------------------------
__global__ void __launch_bounds__(128, 2) attn_mma() {
    const int b = blockIdx.z;
    const int h = blockIdx.y;
    const int t = threadIdx.x;
    const int warp = t >> 5;
    const int lane = t & 31;
    const int g  = lane >> 2;   // 0..7
    const int tg = lane & 3;    // 0..3
    const int qrow0 = blockIdx.x * 64 + warp * 16;
    const size_t bh = (size_t)(b * HH + h) * SS;

    __shared__ unsigned Ks[2][64][68];   // tf32 K bits (4g+tg conflict-free)
    __shared__ unsigned Vs[2][64][72];   // tf32 V bits (8tg+g conflict-free)
    __shared__ unsigned Ps[64][68];      // tf32 P (per-warp 16-row slabs)

    auto load_kv = [&](int kt, int bufi) {
#pragma unroll
        for (int i = 0; i < 8; i++) {
            int idx = t + i * 128;
            int r = idx >> 4;
            int c = (idx & 15) * 4;
            cp16(smem_u32(&Ks[bufi][r][c]), g_k + (bh + kt + r) * DH + c);
            cp16(smem_u32(&Vs[bufi][r][c]), g_v + (bh + kt + r) * DH + c);
        }
    };

    // Q fragments: tf32 bits straight from gmem (already scaled 1/8).
    unsigned qh[8][4];
    {
        const unsigned* Q = g_q + (bh + qrow0) * DH;
#pragma unroll
        for (int kb = 0; kb < 8; kb++) {
            qh[kb][0] = Q[g * DH + kb * 8 + tg];
            qh[kb][1] = Q[(g + 8) * DH + kb * 8 + tg];
            qh[kb][2] = Q[g * DH + kb * 8 + tg + 4];
            qh[kb][3] = Q[(g + 8) * DH + kb * 8 + tg + 4];
        }
    }

    float o[8][4];
#pragma unroll
    for (int ni = 0; ni < 8; ni++)
#pragma unroll
        for (int e = 0; e < 4; e++) o[ni][e] = 0.f;
    float mi0 = -1e30f, mi8 = -1e30f, li0 = 0.f, li8 = 0.f;

    load_kv(0, 0);  CP_COMMIT();
    load_kv(64, 1); CP_COMMIT();

    for (int it = 0; it < 32; it++) {
        CP_WAIT1();
        __syncthreads();
        const int bi = it & 1;

        // S = Q * K^T (single tf32), warp computes 16x64 scores.
        float s[8][4];
#pragma unroll
        for (int ni = 0; ni < 8; ni++)
#pragma unroll
            for (int e = 0; e < 4; e++) s[ni][e] = 0.f;

#pragma unroll
        for (int kb = 0; kb < 8; kb++) {
#pragma unroll
            for (int ni = 0; ni < 8; ni++) {
                unsigned b0h = Ks[bi][ni * 8 + g][kb * 8 + tg];
                unsigned b1h = Ks[bi][ni * 8 + g][kb * 8 + tg + 4];
                mma_tf32(s[ni][0], s[ni][1], s[ni][2], s[ni][3],
                         qh[kb][0], qh[kb][1], qh[kb][2], qh[kb][3], b0h, b1h);
            }
        }

        // Online softmax. Rows: g (elements 0,1) and g+8 (elements 2,3).
        float t0 = mi0, t8 = mi8;
#pragma unroll
        for (int ni = 0; ni < 8; ni++) {
            t0 = fmaxf(t0, fmaxf(s[ni][0], s[ni][1]));
            t8 = fmaxf(t8, fmaxf(s[ni][2], s[ni][3]));
        }
        t0 = fmaxf(t0, __shfl_xor_sync(0xffffffffu, t0, 1));
        t0 = fmaxf(t0, __shfl_xor_sync(0xffffffffu, t0, 2));
        t8 = fmaxf(t8, __shfl_xor_sync(0xffffffffu, t8, 1));
        t8 = fmaxf(t8, __shfl_xor_sync(0xffffffffu, t8, 2));

        float c0 = __expf(mi0 - t0);
        float c8 = __expf(mi8 - t8);
        mi0 = t0; mi8 = t8;
        li0 *= c0; li8 *= c8;

        float rs0 = 0.f, rs8 = 0.f;
#pragma unroll
        for (int ni = 0; ni < 8; ni++) {
            o[ni][0] *= c0; o[ni][1] *= c0;
            o[ni][2] *= c8; o[ni][3] *= c8;
            float p0 = __expf(s[ni][0] - mi0);
            float p1 = __expf(s[ni][1] - mi0);
            float p2 = __expf(s[ni][2] - mi8);
            float p3 = __expf(s[ni][3] - mi8);
            rs0 += p0 + p1;
            rs8 += p2 + p3;
            Ps[warp * 16 + g][ni * 8 + 2 * tg]         = f2tf32(p0);
            Ps[warp * 16 + g][ni * 8 + 2 * tg + 1]     = f2tf32(p1);
            Ps[warp * 16 + 8 + g][ni * 8 + 2 * tg]     = f2tf32(p2);
            Ps[warp * 16 + 8 + g][ni * 8 + 2 * tg + 1] = f2tf32(p3);
        }
        li0 += rs0; li8 += rs8;
        __syncwarp();

        // O += P * V (tf32; P and V already tf32 bits, pure LDS + HMMA).
#pragma unroll
        for (int kb = 0; kb < 8; kb++) {
            unsigned a0 = Ps[warp * 16 + g][kb * 8 + tg];
            unsigned a1 = Ps[warp * 16 + 8 + g][kb * 8 + tg];
            unsigned a2 = Ps[warp * 16 + g][kb * 8 + tg + 4];
            unsigned a3 = Ps[warp * 16 + 8 + g][kb * 8 + tg + 4];
#pragma unroll
            for (int ni = 0; ni < 8; ni++) {
                mma_tf32(o[ni][0], o[ni][1], o[ni][2], o[ni][3],
                         a0, a1, a2, a3,
                         Vs[bi][kb * 8 + tg][ni * 8 + g],
                         Vs[bi][kb * 8 + tg + 4][ni * 8 + g]);
            }
        }

        __syncthreads();
        if (it < 30) load_kv((it + 2) * 64, bi);
        CP_COMMIT();
    }

    li0 += __shfl_xor_sync(0xffffffffu, li0, 1);
    li0 += __shfl_xor_sync(0xffffffffu, li0, 2);
    li8 += __shfl_xor_sync(0xffffffffu, li8, 1);
    li8 += __shfl_xor_sync(0xffffffffu, li8, 2);
    float inv0 = 1.f / li0;
    float inv8 = 1.f / li8;

    // Write attention output as tf32 bits (same value the O-proj would have
    // produced by converting in-loop -> bit-identical final result).
    unsigned* O0 = g_att + ((size_t)b * SS + qrow0 + g) * DD + h * DH;
    unsigned* O8 = g_att + ((size_t)b * SS + qrow0 + 8 + g) * DD + h * DH;
#pragma unroll
    for (int ni = 0; ni < 8; ni++) {
        *(uint2*)(O0 + ni * 8 + 2 * tg) =
            make_uint2(f2tf32(o[ni][0] * inv0), f2tf32(o[ni][1] * inv0));
        *(uint2*)(O8 + ni * 8 + 2 * tg) =
            make_uint2(f2tf32(o[ni][2] * inv8), f2tf32(o[ni][3] * inv8));
    }
}

extern "C" void kernel_launch(void* const* d_in, const int* in_sizes, int n_in,
                              void* d_out, int out_size) {
    const float* x  = (const float*)d_in[0];
    const float* wq = (const float*)d_in[1];
    const float* wk = (const float*)d_in[2];
    const float* wv = (const float*)d_in[3];
    const float* wo = (const float*)d_in[4];
    const float* bo = (const float*)d_in[5];
    float* out = (float*)d_out;

    preconv<<<8192, 256>>>(x, wq, wk, wv, wo);

    dim3 gqkv(DD / 128, MM / 128, 3);   // (8, 32, 3) fused Q/K/V projections
    gemm_tf32<<<gqkv, 256>>>(nullptr, nullptr, 0);

    dim3 ga(SS / 64, HH, BB);           // (32, 16, 2)
    attn_mma<<<ga, 128>>>();

    dim3 go(DD / 128, MM / 128, 1);
    gemm_tf32<<<go, 256>>>(bo, out, 3);
}

// round 15
// speedup vs baseline: 1.0123x; 1.0123x over previous
#include <cuda_runtime.h>
#include <math.h>

#define BB 2
#define SS 2048
#define DD 1024
#define HH 16
#define DH 64
#define MM (BB * SS)   // 4096

// Scratch. ALL inter-kernel tensors hold TF32 BIT PATTERNS, and every
// contraction dimension is stored k-pair-interleaved within 8-col groups:
// position order [c0,c4,c1,c5,c2,c6,c3,c7]. A thread's mma fragment pair
// (k=tg, k=tg+4) is then contiguous -> LDS.64 / LDG.64.
__device__ unsigned g_xt[MM * DD];        // x  (k-perm along DD)
__device__ unsigned g_wt[4][DD * DD];     // wq,wk,wv,wo (k-perm along DD)
__device__ unsigned g_q[BB * HH * SS * DH];   // Q, pre-scaled 1/8, k-perm along DH
__device__ unsigned g_k[BB * HH * SS * DH];   // K, k-perm along DH
__device__ unsigned g_v[BB * HH * SS * DH];   // V, natural order (contraction = row)
__device__ unsigned g_att[MM * DD];           // attn out, k-perm along DD

// ---------------------------------------------------------------------------
// tf32 helpers
// ---------------------------------------------------------------------------
__device__ __forceinline__ unsigned f2tf32(float x) {
    unsigned r;
    asm("cvt.rna.tf32.f32 %0, %1;\n" : "=r"(r) : "f"(x));
    return r;
}
__device__ __forceinline__ void mma_tf32(float& c0, float& c1, float& c2, float& c3,
                                         unsigned a0, unsigned a1, unsigned a2, unsigned a3,
                                         unsigned b0, unsigned b1) {
    asm volatile(
        "mma.sync.aligned.m16n8k8.row.col.f32.tf32.tf32.f32 "
        "{%0,%1,%2,%3}, {%4,%5,%6,%7}, {%8,%9}, {%0,%1,%2,%3};\n"
        : "+f"(c0), "+f"(c1), "+f"(c2), "+f"(c3)
        : "r"(a0), "r"(a1), "r"(a2), "r"(a3), "r"(b0), "r"(b1));
}

// cp.async helpers
__device__ __forceinline__ unsigned smem_u32(const void* p) {
    return (unsigned)__cvta_generic_to_shared(p);
}
__device__ __forceinline__ void cp16(unsigned s, const void* g) {
    asm volatile("cp.async.cg.shared.global [%0], [%1], 16;\n" :: "r"(s), "l"(g));
}
#define CP_COMMIT() asm volatile("cp.async.commit_group;\n" ::: "memory")
#define CP_WAIT1()  asm volatile("cp.async.wait_group 1;\n" ::: "memory")

// ---------------------------------------------------------------------------
// Pre-convert x + 4 weight matrices to tf32 bits with k-pair interleave.
// One work item = one 8-element group along k. 2^20 items total.
// ---------------------------------------------------------------------------
__global__ void __launch_bounds__(256) preconv(const float* __restrict__ x,
                                               const float* __restrict__ wq,
                                               const float* __restrict__ wk,
                                               const float* __restrict__ wv,
                                               const float* __restrict__ wo) {
    unsigned idx = blockIdx.x * 256 + threadIdx.x;   // 0 .. 2^20-1
    const float* src;
    unsigned* dst;
    unsigned off;
    if (idx < (1u << 19)) {              // x: 4M elems = 2^19 groups
        src = x; dst = g_xt; off = idx;
    } else {
        unsigned i2 = idx - (1u << 19);
        unsigned w = i2 >> 17;           // 2^17 groups per W
        off = i2 & 0x1FFFFu;
        src = (w == 0) ? wq : (w == 1) ? wk : (w == 2) ? wv : wo;
        dst = g_wt[w];
    }
    const float* s = src + (size_t)off * 8;
    float4 v0 = *(const float4*)(s);
    float4 v1 = *(const float4*)(s + 4);
    unsigned* d = dst + (size_t)off * 8;
    *(uint4*)(d)     = make_uint4(f2tf32(v0.x), f2tf32(v1.x), f2tf32(v0.y), f2tf32(v1.y));
    *(uint4*)(d + 4) = make_uint4(f2tf32(v0.z), f2tf32(v1.z), f2tf32(v0.w), f2tf32(v1.w));
}

// ---------------------------------------------------------------------------
// NT GEMM, single-tf32, k-pair-interleaved operands -> fragment loads are
// LDS.64. cp.async double-buffered. Stride 40 (8g+2tg conflict-free phases).
// mode 0: fused QKV (z picks W/output); outputs k-perm tf32 bits.
// mode 3: A = g_att, W = g_wt[3], out -> Cext fp32 + bias (natural layout).
// ---------------------------------------------------------------------------
__global__ void __launch_bounds__(256, 2) gemm_tf32(const float* __restrict__ bias,
                                                    float* __restrict__ Cext,
                                                    int mode) {
    __shared__ unsigned As[2][128][40];
    __shared__ unsigned Ws[2][128][40];

    const int t    = threadIdx.x;
    const int lane = t & 31;
    const int warp = t >> 5;
    const int wm   = warp >> 1;
    const int wn   = warp & 1;
    const int g    = lane >> 2;
    const int tg   = lane & 3;

    const int m0 = blockIdx.y * 128;
    const int n0 = blockIdx.x * 128;
    const int z  = blockIdx.z;

    const unsigned* Ap = (mode == 3) ? g_att : g_xt;
    const unsigned* Wp = (mode == 3) ? g_wt[3] : g_wt[z];
    unsigned* Cq = (z == 0) ? g_q : (z == 1) ? g_k : g_v;

    auto load_chunk = [&](int k0, int bufi) {
#pragma unroll
        for (int i = 0; i < 4; i++) {
            int idx = t + i * 256;
            int row = idx >> 3;
            int fc  = (idx & 7) * 4;
            cp16(smem_u32(&As[bufi][row][fc]), Ap + (size_t)(m0 + row) * 1024 + k0 + fc);
            cp16(smem_u32(&Ws[bufi][row][fc]), Wp + (size_t)(n0 + row) * 1024 + k0 + fc);
        }
    };

    float c[2][8][4];
#pragma unroll
    for (int mi = 0; mi < 2; mi++)
#pragma unroll
        for (int ni = 0; ni < 8; ni++)
#pragma unroll
            for (int e = 0; e < 4; e++) c[mi][ni][e] = 0.f;

    load_chunk(0, 0);  CP_COMMIT();
    load_chunk(32, 1); CP_COMMIT();

    for (int kc = 0; kc < 32; kc++) {
        CP_WAIT1();
        __syncthreads();
        const int bi = kc & 1;

#pragma unroll
        for (int kk = 0; kk < 4; kk++) {
            const int kb = kk * 8;
            const int kc2 = kb + 2 * tg;
            unsigned ah[2][4], bh[8][2];
#pragma unroll
            for (int mi = 0; mi < 2; mi++) {
                const int rb = wm * 32 + mi * 16;
                uint2 aA = *(const uint2*)&As[bi][rb + g][kc2];
                uint2 aB = *(const uint2*)&As[bi][rb + g + 8][kc2];
                ah[mi][0] = aA.x; ah[mi][2] = aA.y;
                ah[mi][1] = aB.x; ah[mi][3] = aB.y;
            }
#pragma unroll
            for (int ni = 0; ni < 8; ni++) {
                const int nb = wn * 64 + ni * 8;
                uint2 bb = *(const uint2*)&Ws[bi][nb + g][kc2];
                bh[ni][0] = bb.x; bh[ni][1] = bb.y;
            }
#pragma unroll
            for (int mi = 0; mi < 2; mi++)
#pragma unroll
                for (int ni = 0; ni < 8; ni++) {
                    mma_tf32(c[mi][ni][0], c[mi][ni][1], c[mi][ni][2], c[mi][ni][3],
                             ah[mi][0], ah[mi][1], ah[mi][2], ah[mi][3],
                             bh[ni][0], bh[ni][1]);
                }
        }

        __syncthreads();
        if (kc < 30) load_chunk((kc + 2) * 32, bi);
        CP_COMMIT();
    }

    // Epilogue. mode 0: tf32 bits; Q/K written k-pair-interleaved along dh
    // (scalar stores), V natural (uint2). mode 3: fp32 + bias, natural.
    // pcol = permuted position of col 2tg within its 8-group; pair at +2.
    const int pcol = 2 * ((2 * tg) & 3) + (tg >> 1);
#pragma unroll
    for (int mi = 0; mi < 2; mi++) {
#pragma unroll
        for (int ni = 0; ni < 8; ni++) {
            int mA = m0 + wm * 32 + mi * 16 + g;
            int mB = mA + 8;
            int n  = n0 + wn * 64 + ni * 8 + 2 * tg;
            if (mode == 3) {
                float bx = bias[n], by = bias[n + 1];
                *(float2*)(Cext + (size_t)mA * 1024 + n) =
                    make_float2(c[mi][ni][0] + bx, c[mi][ni][1] + by);
                *(float2*)(Cext + (size_t)mB * 1024 + n) =
                    make_float2(c[mi][ni][2] + bx, c[mi][ni][3] + by);
            } else {
                int h  = n >> 6;
                int grp = (n & 63) & ~7;   // dh group base
                float sc = (z == 0) ? 0.125f : 1.0f;
                int bA = mA >> 11, sA = mA & 2047;
                int bC = mB >> 11, sC = mB & 2047;
                unsigned* rA = Cq + (size_t)((bA * HH + h) * SS + sA) * DH;
                unsigned* rB = Cq + (size_t)((bC * HH + h) * SS + sC) * DH;
                if (z == 2) {
                    int dh = n & 63;
                    *(uint2*)(rA + dh) = make_uint2(f2tf32(c[mi][ni][0]), f2tf32(c[mi][ni][1]));
                    *(uint2*)(rB + dh) = make_uint2(f2tf32(c[mi][ni][2]), f2tf32(c[mi][ni][3]));
                } else {
                    rA[grp + pcol]     = f2tf32(c[mi][ni][0] * sc);
                    rA[grp + pcol + 2] = f2tf32(c[mi][ni][1] * sc);
                    rB[grp + pcol]     = f2tf32(c[mi][ni][2] * sc);
                    rB[grp + pcol + 2] = f2tf32(c[mi][ni][3] * sc);
                }
            }
        }
    }
}

// ---------------------------------------------------------------------------
// Flash attention, tf32 mma, k-pair-interleaved Q/K and Ps -> LDS.64
// fragment loads. cp.async double-buffered K/V. Block = 64 q-rows, 4 warps.
// Writes g_att as k-perm tf32 bits for the O-projection.
// ---------------------------------------------------------------------------
__global__ void __launch_bounds__(128, 2) attn_mma() {
    const int b = blockIdx.z;
    const int h = blockIdx.y;
    const int t = threadIdx.x;
    const int warp = t >> 5;
    const int lane = t & 31;
    const int g  = lane >> 2;   // 0..7
    const int tg = lane & 3;    // 0..3
    const int qrow0 = blockIdx.x * 64 + warp * 16;
    const size_t bh = (size_t)(b * HH + h) * SS;
    const int pcol = 2 * ((2 * tg) & 3) + (tg >> 1);

    __shared__ unsigned Ks[2][64][72];   // k-perm K bits; LDS.64 conflict-free
    __shared__ unsigned Vs[2][64][72];   // natural V bits; 8tg+g conflict-free
    __shared__ unsigned Ps[64][72];      // k-perm P (per-warp 16-row slabs)

    auto load_kv = [&](int kt, int bufi) {
#pragma unroll
        for (int i = 0; i < 8; i++) {
            int idx = t + i * 128;
            int r = idx >> 4;
            int c = (idx & 15) * 4;
            cp16(smem_u32(&Ks[bufi][r][c]), g_k + (bh + kt + r) * DH + c);
            cp16(smem_u32(&Vs[bufi][r][c]), g_v + (bh + kt + r) * DH + c);
        }
    };

    // Q fragments: k-perm gmem -> uint2 loads (already scaled 1/8).
    unsigned qh[8][4];
    {
        const unsigned* Q = g_q + (bh + qrow0) * DH;
#pragma unroll
        for (int kb = 0; kb < 8; kb++) {
            uint2 qA = *(const uint2*)(Q + g * DH + kb * 8 + 2 * tg);
            uint2 qB = *(const uint2*)(Q + (g + 8) * DH + kb * 8 + 2 * tg);
            qh[kb][0] = qA.x; qh[kb][2] = qA.y;
            qh[kb][1] = qB.x; qh[kb][3] = qB.y;
        }
    }

    float o[8][4];
#pragma unroll
    for (int ni = 0; ni < 8; ni++)
#pragma unroll
        for (int e = 0; e < 4; e++) o[ni][e] = 0.f;
    float mi0 = -1e30f, mi8 = -1e30f, li0 = 0.f, li8 = 0.f;

    load_kv(0, 0);  CP_COMMIT();
    load_kv(64, 1); CP_COMMIT();

    for (int it = 0; it < 32; it++) {
        CP_WAIT1();
        __syncthreads();
        const int bi = it & 1;

        // S = Q * K^T (single tf32), K fragments via LDS.64.
        float s[8][4];
#pragma unroll
        for (int ni = 0; ni < 8; ni++)
#pragma unroll
            for (int e = 0; e < 4; e++) s[ni][e] = 0.f;

#pragma unroll
        for (int kb = 0; kb < 8; kb++) {
#pragma unroll
            for (int ni = 0; ni < 8; ni++) {
                uint2 bb = *(const uint2*)&Ks[bi][ni * 8 + g][kb * 8 + 2 * tg];
                mma_tf32(s[ni][0], s[ni][1], s[ni][2], s[ni][3],
                         qh[kb][0], qh[kb][1], qh[kb][2], qh[kb][3], bb.x, bb.y);
            }
        }

        // Online softmax. Rows: g (elements 0,1) and g+8 (elements 2,3).
        float t0 = mi0, t8 = mi8;
#pragma unroll
        for (int ni = 0; ni < 8; ni++) {
            t0 = fmaxf(t0, fmaxf(s[ni][0], s[ni][1]));
            t8 = fmaxf(t8, fmaxf(s[ni][2], s[ni][3]));
        }
        t0 = fmaxf(t0, __shfl_xor_sync(0xffffffffu, t0, 1));
        t0 = fmaxf(t0, __shfl_xor_sync(0xffffffffu, t0, 2));
        t8 = fmaxf(t8, __shfl_xor_sync(0xffffffffu, t8, 1));
        t8 = fmaxf(t8, __shfl_xor_sync(0xffffffffu, t8, 2));

        float c0 = __expf(mi0 - t0);
        float c8 = __expf(mi8 - t8);
        mi0 = t0; mi8 = t8;
        li0 *= c0; li8 *= c8;

        float rs0 = 0.f, rs8 = 0.f;
#pragma unroll
        for (int ni = 0; ni < 8; ni++) {
            o[ni][0] *= c0; o[ni][1] *= c0;
            o[ni][2] *= c8; o[ni][3] *= c8;
            float p0 = __expf(s[ni][0] - mi0);
            float p1 = __expf(s[ni][1] - mi0);
            float p2 = __expf(s[ni][2] - mi8);
            float p3 = __expf(s[ni][3] - mi8);
            rs0 += p0 + p1;
            rs8 += p2 + p3;
            // k-perm store: col 2tg -> pcol, col 2tg+1 -> pcol+2 (banks distinct)
            Ps[warp * 16 + g][ni * 8 + pcol]         = f2tf32(p0);
            Ps[warp * 16 + g][ni * 8 + pcol + 2]     = f2tf32(p1);
            Ps[warp * 16 + 8 + g][ni * 8 + pcol]     = f2tf32(p2);
            Ps[warp * 16 + 8 + g][ni * 8 + pcol + 2] = f2tf32(p3);
        }
        li0 += rs0; li8 += rs8;
        __syncwarp();

        // O += P * V. P fragments via LDS.64 (k-perm); V rows natural.
#pragma unroll
        for (int kb = 0; kb < 8; kb++) {
            uint2 pA = *(const uint2*)&Ps[warp * 16 + g][kb * 8 + 2 * tg];
            uint2 pB = *(const uint2*)&Ps[warp * 16 + 8 + g][kb * 8 + 2 * tg];
#pragma unroll
            for (int ni = 0; ni < 8; ni++) {
                mma_tf32(o[ni][0], o[ni][1], o[ni][2], o[ni][3],
                         pA.x, pB.x, pA.y, pB.y,
                         Vs[bi][kb * 8 + tg][ni * 8 + g],
                         Vs[bi][kb * 8 + tg + 4][ni * 8 + g]);
            }
        }

        __syncthreads();
        if (it < 30) load_kv((it + 2) * 64, bi);
        CP_COMMIT();
    }

    li0 += __shfl_xor_sync(0xffffffffu, li0, 1);
    li0 += __shfl_xor_sync(0xffffffffu, li0, 2);
    li8 += __shfl_xor_sync(0xffffffffu, li8, 1);
    li8 += __shfl_xor_sync(0xffffffffu, li8, 2);
    float inv0 = 1.f / li0;
    float inv8 = 1.f / li8;

    // Write attention output as k-perm tf32 bits (cols h*64 + ni*8 group).
    unsigned* O0 = g_att + ((size_t)b * SS + qrow0 + g) * DD + h * DH;
    unsigned* O8 = g_att + ((size_t)b * SS + qrow0 + 8 + g) * DD + h * DH;
#pragma unroll
    for (int ni = 0; ni < 8; ni++) {
        O0[ni * 8 + pcol]     = f2tf32(o[ni][0] * inv0);
        O0[ni * 8 + pcol + 2] = f2tf32(o[ni][1] * inv0);
        O8[ni * 8 + pcol]     = f2tf32(o[ni][2] * inv8);
        O8[ni * 8 + pcol + 2] = f2tf32(o[ni][3] * inv8);
    }
}

extern "C" void kernel_launch(void* const* d_in, const int* in_sizes, int n_in,
                              void* d_out, int out_size) {
    const float* x  = (const float*)d_in[0];
    const float* wq = (const float*)d_in[1];
    const float* wk = (const float*)d_in[2];
    const float* wv = (const float*)d_in[3];
    const float* wo = (const float*)d_in[4];
    const float* bo = (const float*)d_in[5];
    float* out = (float*)d_out;

    preconv<<<4096, 256>>>(x, wq, wk, wv, wo);

    dim3 gqkv(DD / 128, MM / 128, 3);   // (8, 32, 3) fused Q/K/V projections
    gemm_tf32<<<gqkv, 256>>>(nullptr, nullptr, 0);

    dim3 ga(SS / 64, HH, BB);           // (32, 16, 2)
    attn_mma<<<ga, 128>>>();

    dim3 go(DD / 128, MM / 128, 1);
    gemm_tf32<<<go, 256>>>(bo, out, 3);
}